// round 4
// baseline (speedup 1.0000x reference)
#include <cuda_runtime.h>
#include <math_constants.h>

// RightPool: out[b,c,h,w] = max(x[b,c,h,0..w]) — inclusive cummax along last
// axis, W = 128, fp32. Tensor (8,256,128,128) -> 262,144 rows of 128 floats.
//
// R3 -> R4: software-pipelined grid-stride loop. Each warp owns ~8 groups of
// R=4 rows; while it scans/stores group g, the loads for group g+stride are
// already in flight (prefetched before the scan). This keeps per-warp memory
// pressure continuous instead of load-burst -> dead scan window -> store.

static constexpr int W = 128;           // row length (elements)
static constexpr int R = 4;             // rows per group (per warp per step)
static constexpr int WARPS_PER_BLOCK = 8;
static constexpr int THREADS = WARPS_PER_BLOCK * 32;
static constexpr int GROUPS_PER_WARP = 8;   // target pipeline depth per warp

__device__ __forceinline__ float4 ldcs4(const float* p) {
    return __ldcs(reinterpret_cast<const float4*>(p));
}

// Scan + combine + store one group of R rows held in v[].
__device__ __forceinline__ void process_group(float4 (&v)[R], float* out,
                                              size_t base, int lane) {
    // Local inclusive prefix max (in place).
    #pragma unroll
    for (int r = 0; r < R; r++) {
        v[r].y = fmaxf(v[r].x, v[r].y);
        v[r].z = fmaxf(v[r].y, v[r].z);
        v[r].w = fmaxf(v[r].z, v[r].w);
    }
    // Interleaved warp-level inclusive max-scans of lane totals.
    float s[R];
    #pragma unroll
    for (int r = 0; r < R; r++) s[r] = v[r].w;
    #pragma unroll
    for (int ofs = 1; ofs < 32; ofs <<= 1) {
        float n[R];
        #pragma unroll
        for (int r = 0; r < R; r++) n[r] = __shfl_up_sync(0xFFFFFFFFu, s[r], ofs);
        #pragma unroll
        for (int r = 0; r < R; r++) s[r] = fmaxf(s[r], n[r]);
    }
    // Exclusive prefix, combine, store.
    #pragma unroll
    for (int r = 0; r < R; r++) {
        float e = __shfl_up_sync(0xFFFFFFFFu, s[r], 1);
        if (lane == 0) e = -CUDART_INF_F;
        float4 o;
        o.x = fmaxf(e, v[r].x);
        o.y = fmaxf(e, v[r].y);
        o.z = fmaxf(e, v[r].z);
        o.w = fmaxf(e, v[r].w);
        *reinterpret_cast<float4*>(out + base + (size_t)r * W) = o;
    }
}

__global__ __launch_bounds__(THREADS)
void rightpool_kernel(const float* __restrict__ x,
                      float* __restrict__ out,
                      int num_groups) {
    const int lane   = threadIdx.x & 31;
    const int gwarp  = blockIdx.x * WARPS_PER_BLOCK + (threadIdx.x >> 5);
    const int stride = gridDim.x * WARPS_PER_BLOCK;

    int g = gwarp;
    if (g >= num_groups) return;

    const size_t lane_off = (size_t)lane * 4;
    size_t base = (size_t)g * (R * W) + lane_off;

    // Prologue: load first group.
    float4 v[R];
    #pragma unroll
    for (int r = 0; r < R; r++)
        v[r] = ldcs4(x + base + (size_t)r * W);

    // Pipelined loop: prefetch next group, then process current.
    for (;;) {
        const int gn = g + stride;
        const bool has_next = gn < num_groups;
        float4 vn[R];
        size_t base_n = (size_t)gn * (R * W) + lane_off;
        if (has_next) {
            #pragma unroll
            for (int r = 0; r < R; r++)
                vn[r] = ldcs4(x + base_n + (size_t)r * W);
        }

        process_group(v, out, base, lane);

        if (!has_next) break;
        #pragma unroll
        for (int r = 0; r < R; r++) v[r] = vn[r];
        g = gn;
        base = base_n;
    }
}

// Tail kernel: one warp per leftover row (not used for the bench shape).
__global__ __launch_bounds__(256)
void rightpool_tail_kernel(const float* __restrict__ x,
                           float* __restrict__ out,
                           int first_row, int num_rows) {
    const int lane = threadIdx.x & 31;
    const int row  = first_row + blockIdx.x * 8 + (threadIdx.x >> 5);
    if (row >= num_rows) return;
    const size_t base = (size_t)row * W + (size_t)lane * 4;
    float4 v = ldcs4(x + base);
    v.y = fmaxf(v.x, v.y); v.z = fmaxf(v.y, v.z); v.w = fmaxf(v.z, v.w);
    float s = v.w;
    #pragma unroll
    for (int ofs = 1; ofs < 32; ofs <<= 1)
        s = fmaxf(s, __shfl_up_sync(0xFFFFFFFFu, s, ofs));
    float e = __shfl_up_sync(0xFFFFFFFFu, s, 1);
    if (lane == 0) e = -CUDART_INF_F;
    float4 o = {fmaxf(e, v.x), fmaxf(e, v.y), fmaxf(e, v.z), fmaxf(e, v.w)};
    *reinterpret_cast<float4*>(out + base) = o;
}

extern "C" void kernel_launch(void* const* d_in, const int* in_sizes, int n_in,
                              void* d_out, int out_size) {
    const float* x = (const float*)d_in[0];
    float* out = (float*)d_out;
    const int n = in_sizes[0];
    const int num_rows = n / W;

    const int num_groups = num_rows / R;
    // Size grid so each warp runs ~GROUPS_PER_WARP pipeline steps.
    int total_warps = (num_groups + GROUPS_PER_WARP - 1) / GROUPS_PER_WARP;
    int blocks = (total_warps + WARPS_PER_BLOCK - 1) / WARPS_PER_BLOCK;
    if (blocks < 1) blocks = 1;
    rightpool_kernel<<<blocks, THREADS>>>(x, out, num_groups);

    const int tail_rows = num_rows - num_groups * R;
    if (tail_rows > 0) {
        const int tail_blocks = (tail_rows + 7) / 8;
        rightpool_tail_kernel<<<tail_blocks, 256>>>(x, out,
                                                    num_groups * R, num_rows);
    }
}

// round 5
// speedup vs baseline: 1.0858x; 1.0858x over previous
#include <cuda_runtime.h>
#include <math_constants.h>

// RightPool: out[b,c,h,w] = max(x[b,c,h,0..w]) — inclusive cummax along last
// axis, W = 128, fp32. Tensor (8,256,128,128) -> 262,144 rows of 128 floats.
//
// R4 -> R5: Blackwell 256-bit vector loads/stores. Half-warp per row:
// lane h = lane&15 owns elements [8h, 8h+8) via ONE ld.global.v8.b32 (32B).
// A warp covers 2 rows per vector instruction (1KB dense). Warp processes
// 4 rows (2 row-pairs front-batched, MLP=2x1KB). Scan is width-16 (4 steps).

static constexpr int W = 128;            // row length (elements)
static constexpr int ROWS_PER_WARP = 4;  // 2 pairs x 2 rows
static constexpr int WARPS_PER_BLOCK = 8;
static constexpr int THREADS = WARPS_PER_BLOCK * 32;
static constexpr int ROWS_PER_BLOCK = WARPS_PER_BLOCK * ROWS_PER_WARP;

__device__ __forceinline__ void ldg256(const float* p, float a[8]) {
    asm volatile(
        "ld.global.v8.b32 {%0,%1,%2,%3,%4,%5,%6,%7}, [%8];"
        : "=f"(a[0]), "=f"(a[1]), "=f"(a[2]), "=f"(a[3]),
          "=f"(a[4]), "=f"(a[5]), "=f"(a[6]), "=f"(a[7])
        : "l"(p));
}

__device__ __forceinline__ void stg256(float* p, const float a[8]) {
    asm volatile(
        "st.global.v8.b32 [%8], {%0,%1,%2,%3,%4,%5,%6,%7};"
        :: "f"(a[0]), "f"(a[1]), "f"(a[2]), "f"(a[3]),
           "f"(a[4]), "f"(a[5]), "f"(a[6]), "f"(a[7]),
           "l"(p)
        : "memory");
}

__global__ __launch_bounds__(THREADS)
void rightpool_kernel(const float* __restrict__ x,
                      float* __restrict__ out,
                      int num_rows) {
    const int lane = threadIdx.x & 31;
    const int half = lane >> 4;          // which row of the pair
    const int h    = lane & 15;          // position within the row (16 lanes)
    const int warp = blockIdx.x * WARPS_PER_BLOCK + (threadIdx.x >> 5);
    const int row0 = warp * ROWS_PER_WARP;
    if (row0 >= num_rows) return;

    // This thread's element base for pair p: row (row0 + 2p + half), elems [8h, 8h+8).
    const size_t tbase = (size_t)(row0 + half) * W + (size_t)h * 8;

    // ---- Front-batched 256-bit loads: 2 independent LDG.256 (1KB each) ----
    float a[2][8];
    #pragma unroll
    for (int p = 0; p < 2; p++)
        ldg256(x + tbase + (size_t)(2 * p) * W, a[p]);

    // In-place local inclusive prefix max over the 8 owned elements.
    #pragma unroll
    for (int p = 0; p < 2; p++)
        #pragma unroll
        for (int i = 1; i < 8; i++)
            a[p][i] = fmaxf(a[p][i - 1], a[p][i]);

    // Width-16 inclusive max-scan of segment totals (a[p][7]) across the
    // half-warp. shfl_up with width=16 returns own value when h < ofs, and
    // fmax(s,s)=s, so no predicate.
    float s[2];
    #pragma unroll
    for (int p = 0; p < 2; p++) s[p] = a[p][7];

    #pragma unroll
    for (int ofs = 1; ofs < 16; ofs <<= 1) {
        float n[2];
        #pragma unroll
        for (int p = 0; p < 2; p++)
            n[p] = __shfl_up_sync(0xFFFFFFFFu, s[p], ofs, 16);
        #pragma unroll
        for (int p = 0; p < 2; p++) s[p] = fmaxf(s[p], n[p]);
    }

    // Exclusive prefix per segment, combine, 256-bit store.
    #pragma unroll
    for (int p = 0; p < 2; p++) {
        float e = __shfl_up_sync(0xFFFFFFFFu, s[p], 1, 16);
        if (h == 0) e = -CUDART_INF_F;
        float o[8];
        #pragma unroll
        for (int i = 0; i < 8; i++) o[i] = fmaxf(e, a[p][i]);
        stg256(out + tbase + (size_t)(2 * p) * W, o);
    }
}

// Tail kernel: one warp per leftover row (unused for the bench shape).
__global__ __launch_bounds__(256)
void rightpool_tail_kernel(const float* __restrict__ x,
                           float* __restrict__ out,
                           int first_row, int num_rows) {
    const int lane = threadIdx.x & 31;
    const int row  = first_row + blockIdx.x * 8 + (threadIdx.x >> 5);
    if (row >= num_rows) return;
    const size_t base = (size_t)row * W + (size_t)lane * 4;
    float4 v = *reinterpret_cast<const float4*>(x + base);
    v.y = fmaxf(v.x, v.y); v.z = fmaxf(v.y, v.z); v.w = fmaxf(v.z, v.w);
    float s = v.w;
    #pragma unroll
    for (int ofs = 1; ofs < 32; ofs <<= 1)
        s = fmaxf(s, __shfl_up_sync(0xFFFFFFFFu, s, ofs));
    float e = __shfl_up_sync(0xFFFFFFFFu, s, 1);
    if (lane == 0) e = -CUDART_INF_F;
    float4 o = {fmaxf(e, v.x), fmaxf(e, v.y), fmaxf(e, v.z), fmaxf(e, v.w)};
    *reinterpret_cast<float4*>(out + base) = o;
}

extern "C" void kernel_launch(void* const* d_in, const int* in_sizes, int n_in,
                              void* d_out, int out_size) {
    const float* x = (const float*)d_in[0];
    float* out = (float*)d_out;
    const int n = in_sizes[0];
    const int num_rows = n / W;

    const int full_rows = (num_rows / ROWS_PER_WARP) * ROWS_PER_WARP;
    const int blocks = (full_rows + ROWS_PER_BLOCK - 1) / ROWS_PER_BLOCK;
    if (blocks > 0)
        rightpool_kernel<<<blocks, THREADS>>>(x, out, full_rows);

    const int tail_rows = num_rows - full_rows;
    if (tail_rows > 0) {
        const int tail_blocks = (tail_rows + 7) / 8;
        rightpool_tail_kernel<<<tail_blocks, 256>>>(x, out, full_rows, num_rows);
    }
}

// round 6
// speedup vs baseline: 1.0881x; 1.0021x over previous
#include <cuda_runtime.h>
#include <math_constants.h>

// RightPool: out[b,c,h,w] = max(x[b,c,h,0..w]) — inclusive cummax along last
// axis, W = 128, fp32. Tensor (8,256,128,128) -> 262,144 rows of 128 floats.
//
// R5 -> R6: combine the two best configs. 256-bit vector ld/st (half-warp per
// row, lane h owns 8 elems) AND 4 front-batched LDG.256 per warp (8 rows,
// MLP_p1=4 — the geometry that won R2). 32-bit byte-offset indexing to cut
// the IMAD.WIDE address math (alu was 15.9%).

static constexpr int W = 128;            // row length (elements)
static constexpr int PAIRS = 4;          // row-pairs per warp (MLP_p1 = 4)
static constexpr int ROWS_PER_WARP = 2 * PAIRS;
static constexpr int WARPS_PER_BLOCK = 8;
static constexpr int THREADS = WARPS_PER_BLOCK * 32;
static constexpr int ROWS_PER_BLOCK = WARPS_PER_BLOCK * ROWS_PER_WARP;

__device__ __forceinline__ void ldg256(const char* p, float a[8]) {
    asm volatile(
        "ld.global.v8.b32 {%0,%1,%2,%3,%4,%5,%6,%7}, [%8];"
        : "=f"(a[0]), "=f"(a[1]), "=f"(a[2]), "=f"(a[3]),
          "=f"(a[4]), "=f"(a[5]), "=f"(a[6]), "=f"(a[7])
        : "l"(p));
}

__device__ __forceinline__ void stg256(char* p, const float a[8]) {
    asm volatile(
        "st.global.v8.b32 [%8], {%0,%1,%2,%3,%4,%5,%6,%7};"
        :: "f"(a[0]), "f"(a[1]), "f"(a[2]), "f"(a[3]),
           "f"(a[4]), "f"(a[5]), "f"(a[6]), "f"(a[7]),
           "l"(p)
        : "memory");
}

__global__ __launch_bounds__(THREADS)
void rightpool_kernel(const float* __restrict__ x,
                      float* __restrict__ out,
                      int num_rows) {
    const int lane = threadIdx.x & 31;
    const int half = lane >> 4;          // which row of the pair
    const int h    = lane & 15;          // position within the row (16 lanes)
    const int warp = blockIdx.x * WARPS_PER_BLOCK + (threadIdx.x >> 5);
    const int row0 = warp * ROWS_PER_WARP;
    if (row0 >= num_rows) return;

    // 32-bit BYTE offsets (tensor is 128 MiB; max offset < 2^31).
    // Thread base: row (row0 + half), elements [8h, 8h+8).
    const unsigned tbyte = (unsigned)(row0 + half) * (W * 4) + (unsigned)h * 32;
    const char* xb  = reinterpret_cast<const char*>(x) + tbyte;
    char*       ob  = reinterpret_cast<char*>(out) + tbyte;
    constexpr unsigned PAIR_STRIDE = 2u * W * 4u;   // 1024 bytes

    // ---- Front-batched loads: 4 independent LDG.256 (MLP_p1 = 4) ----
    float a[PAIRS][8];
    #pragma unroll
    for (int p = 0; p < PAIRS; p++)
        ldg256(xb + p * PAIR_STRIDE, a[p]);

    // In-place local inclusive prefix max over the 8 owned elements.
    #pragma unroll
    for (int p = 0; p < PAIRS; p++)
        #pragma unroll
        for (int i = 1; i < 8; i++)
            a[p][i] = fmaxf(a[p][i - 1], a[p][i]);

    // Width-16 inclusive max-scan of segment totals across the half-warp.
    // shfl_up(width=16) returns own value when h < ofs; fmax(s,s)=s.
    float s[PAIRS];
    #pragma unroll
    for (int p = 0; p < PAIRS; p++) s[p] = a[p][7];

    #pragma unroll
    for (int ofs = 1; ofs < 16; ofs <<= 1) {
        float n[PAIRS];
        #pragma unroll
        for (int p = 0; p < PAIRS; p++)
            n[p] = __shfl_up_sync(0xFFFFFFFFu, s[p], ofs, 16);
        #pragma unroll
        for (int p = 0; p < PAIRS; p++) s[p] = fmaxf(s[p], n[p]);
    }

    // Exclusive prefix per segment, combine, 256-bit store.
    #pragma unroll
    for (int p = 0; p < PAIRS; p++) {
        float e = __shfl_up_sync(0xFFFFFFFFu, s[p], 1, 16);
        if (h == 0) e = -CUDART_INF_F;
        float o[8];
        #pragma unroll
        for (int i = 0; i < 8; i++) o[i] = fmaxf(e, a[p][i]);
        stg256(ob + p * PAIR_STRIDE, o);
    }
}

// Tail kernel: one warp per leftover row (unused for the bench shape).
__global__ __launch_bounds__(256)
void rightpool_tail_kernel(const float* __restrict__ x,
                           float* __restrict__ out,
                           int first_row, int num_rows) {
    const int lane = threadIdx.x & 31;
    const int row  = first_row + blockIdx.x * 8 + (threadIdx.x >> 5);
    if (row >= num_rows) return;
    const size_t base = (size_t)row * W + (size_t)lane * 4;
    float4 v = *reinterpret_cast<const float4*>(x + base);
    v.y = fmaxf(v.x, v.y); v.z = fmaxf(v.y, v.z); v.w = fmaxf(v.z, v.w);
    float s = v.w;
    #pragma unroll
    for (int ofs = 1; ofs < 32; ofs <<= 1)
        s = fmaxf(s, __shfl_up_sync(0xFFFFFFFFu, s, ofs));
    float e = __shfl_up_sync(0xFFFFFFFFu, s, 1);
    if (lane == 0) e = -CUDART_INF_F;
    float4 o = {fmaxf(e, v.x), fmaxf(e, v.y), fmaxf(e, v.z), fmaxf(e, v.w)};
    *reinterpret_cast<float4*>(out + base) = o;
}

extern "C" void kernel_launch(void* const* d_in, const int* in_sizes, int n_in,
                              void* d_out, int out_size) {
    const float* x = (const float*)d_in[0];
    float* out = (float*)d_out;
    const int n = in_sizes[0];
    const int num_rows = n / W;

    const int full_rows = (num_rows / ROWS_PER_WARP) * ROWS_PER_WARP;
    const int blocks = (full_rows + ROWS_PER_BLOCK - 1) / ROWS_PER_BLOCK;
    if (blocks > 0)
        rightpool_kernel<<<blocks, THREADS>>>(x, out, full_rows);

    const int tail_rows = num_rows - full_rows;
    if (tail_rows > 0) {
        const int tail_blocks = (tail_rows + 7) / 8;
        rightpool_tail_kernel<<<tail_blocks, 256>>>(x, out, full_rows, num_rows);
    }
}